// round 16
// baseline (speedup 1.0000x reference)
#include <cuda_runtime.h>
#include <cuda_fp16.h>
#include <cstdint>

#define FULLMASK 0xffffffffu
#define R_TOT 65536

// approx scores are scaled by (2^4)*(2^8) = 4096
#define Q_SCALE  16.0f
#define K_SCALE  256.0f
#define EPS_SC   64.0f   // window (scaled): >= 2*(hh-only approx err + fp16 quant)
#define NCP      17      // per-segment staged-candidate cap; 5 CTA/SM incl 1KB overhead

// ---------------- device scratch (no allocs allowed) ----------------
__device__ __align__(16) __half g_scoresh[(size_t)R_TOT * 2048];   // 256MB approx
__device__ __align__(16) float g_qn[(size_t)R_TOT * 256];          // exact q_norm
__device__ __align__(16) __half g_qh[(size_t)2 * R_TOT * 128];
__device__ __align__(16) __half g_kh[2 * 1024 * 128];

// Joint candidates: (i+1)*(j+1) <= 16 -> 50 cells
__constant__ unsigned char c_CI[50] = {
    0,0,0,0,0,0,0,0,0,0,0,0,0,0,0,0, 1,1,1,1,1,1,1,1, 2,2,2,2,2,
    3,3,3,3, 4,4,4, 5,5, 6,6, 7,7, 8,9,10,11,12,13,14,15
};
__constant__ unsigned char c_CJ[50] = {
    0,1,2,3,4,5,6,7,8,9,10,11,12,13,14,15, 0,1,2,3,4,5,6,7, 0,1,2,3,4,
    0,1,2,3, 0,1,2, 0,1, 0,1, 0,1, 0,0,0,0,0,0,0,0
};

__device__ __forceinline__ unsigned fmono(float f) {
    unsigned u = __float_as_uint(f);
    return u ^ (unsigned)(((int)u >> 31) | (int)0x80000000);
}
__device__ __forceinline__ float funmono(unsigned m) {
    return __uint_as_float((m & 0x80000000u) ? (m ^ 0x80000000u) : ~m);
}

// ---------------------------------------------------------------------------
// K1: LayerNorm — BIT-EXACT R1/R5 numerics. Writes exact fp32 q_norm and
// scaled fp16 (hi term only) for the HMMA oracle.
// ---------------------------------------------------------------------------
__global__ __launch_bounds__(256)
void pkr_ln(const float* __restrict__ query,
            const float* __restrict__ gma,
            const float* __restrict__ bta)
{
    const int tid = threadIdx.x;
    const int r = tid >> 3, g = tid & 7;
    const int row = blockIdx.x * 32 + r;

    const float4* qp = (const float4*)(query + (size_t)row * 256);
    float4 v[8];
    float s = 0.f;
#pragma unroll
    for (int j = 0; j < 8; j++) {
        v[j] = qp[j * 8 + g];
        s += (v[j].x + v[j].y) + (v[j].z + v[j].w);
    }
#pragma unroll
    for (int off = 4; off >= 1; off >>= 1)
        s += __shfl_xor_sync(FULLMASK, s, off, 8);
    const float mu = s * (1.f / 256.f);

    float s2 = 0.f;
#pragma unroll
    for (int j = 0; j < 8; j++) {
        float dx = v[j].x - mu, dy = v[j].y - mu;
        float dz = v[j].z - mu, dw = v[j].w - mu;
        s2 += (dx * dx + dy * dy) + (dz * dz + dw * dw);
    }
#pragma unroll
    for (int off = 4; off >= 1; off >>= 1)
        s2 += __shfl_xor_sync(FULLMASK, s2, off, 8);

    const float varp = s2 * (1.f / 256.f) + 1e-5f;
    float rs = rsqrtf(varp);
    rs = rs * (1.5f - 0.5f * varp * rs * rs);

#pragma unroll
    for (int j = 0; j < 8; j++) {
        const int c = j * 32 + g * 4;
        float d0 = (v[j].x - mu) * rs * gma[c + 0] + bta[c + 0];
        float d1 = (v[j].y - mu) * rs * gma[c + 1] + bta[c + 1];
        float d2 = (v[j].z - mu) * rs * gma[c + 2] + bta[c + 2];
        float d3 = (v[j].w - mu) * rs * gma[c + 3] + bta[c + 3];

        *(float4*)(g_qn + (size_t)row * 256 + c) = make_float4(d0, d1, d2, d3);

        union { __half b[4]; uint2 u; } ph;
        ph.b[0] = __float2half_rn(d0 * Q_SCALE);
        ph.b[1] = __float2half_rn(d1 * Q_SCALE);
        ph.b[2] = __float2half_rn(d2 * Q_SCALE);
        ph.b[3] = __float2half_rn(d3 * Q_SCALE);
        const int half = c >> 7, kl = c & 127;
        *(uint2*)(g_qh + (size_t)half * R_TOT * 128 + (size_t)row * 128 + kl) = ph.u;
    }
}

// ---------------------------------------------------------------------------
// K2: scaled fp16 (hi only) of both key matrices.
// ---------------------------------------------------------------------------
__global__ void pkr_kprep(const float* __restrict__ ck, const float* __restrict__ cp)
{
    const int idx = blockIdx.x * 256 + threadIdx.x;      // 0..262143
    float vv = ((idx < 131072) ? ck[idx] : cp[idx - 131072]) * K_SCALE;
    g_kh[idx] = __float2half_rn(vv);
}

// ---------------------------------------------------------------------------
// K3: 1-product fp16 HMMA GEMM (approx oracle). BM=128, BN=64, 8 warps.
// ---------------------------------------------------------------------------
#define MMA16816(d, a, b)                                                       \
    asm volatile("mma.sync.aligned.m16n8k16.row.col.f32.f16.f16.f32 "           \
                 "{%0,%1,%2,%3}, {%4,%5,%6,%7}, {%8,%9}, {%0,%1,%2,%3};"        \
                 : "+f"(d[0]), "+f"(d[1]), "+f"(d[2]), "+f"(d[3])               \
                 : "r"(a[0]), "r"(a[1]), "r"(a[2]), "r"(a[3]),                  \
                   "r"(b[0]), "r"(b[1]))

__device__ __forceinline__ void ldmx4(unsigned* r, unsigned addr) {
    asm volatile("ldmatrix.sync.aligned.m8n8.x4.shared.b16 {%0,%1,%2,%3}, [%4];"
                 : "=r"(r[0]), "=r"(r[1]), "=r"(r[2]), "=r"(r[3]) : "r"(addr));
}
__device__ __forceinline__ void ldmx2(unsigned* r, unsigned addr) {
    asm volatile("ldmatrix.sync.aligned.m8n8.x2.shared.b16 {%0,%1}, [%2];"
                 : "=r"(r[0]), "=r"(r[1]) : "r"(addr));
}

__global__ __launch_bounds__(256, 4)
void pkr_mma(void)
{
    extern __shared__ char sm[];
    // Ah 0..32K, Bh 32K..48K
    const unsigned sA0 = (unsigned)__cvta_generic_to_shared(sm);
    const unsigned sB0 = sA0 + 32768;

    const int tid  = threadIdx.x;
    const int half = blockIdx.x >> 4;
    const int nb   = blockIdx.x & 15;
    const int rowBase = blockIdx.y * 128;

    {
        const int r = tid >> 1, c0 = (tid & 1) * 8;
        const uint4* glh = (const uint4*)(g_qh + (size_t)half * R_TOT * 128
                                          + (size_t)(rowBase + r) * 128);
        char* base = sm + r * 256;
#pragma unroll
        for (int i = 0; i < 8; i++) {
            const int c = c0 + i, cp = c ^ (r & 7);
            *(uint4*)(base + cp * 16) = glh[c];
        }
    }
    {
        const int r = tid >> 2, c0 = (tid & 3) * 4;
        const uint4* glh = (const uint4*)(g_kh + (size_t)half * 1024 * 128
                                          + (size_t)(nb * 64 + r) * 128);
        char* base = sm + 32768 + r * 256;
#pragma unroll
        for (int i = 0; i < 4; i++) {
            const int c = c0 + i, cp = c ^ (r & 7);
            *(uint4*)(base + cp * 16) = glh[c];
        }
    }
    __syncthreads();

    const int warp = tid >> 5, lane = tid & 31;
    const int wm = (warp >> 1) * 32;
    const int wn = (warp & 1) * 32;
    const int sel = lane >> 3;

    const int rA0 = wm + (lane & 7) + ((sel & 1) << 3);
    const int khA = sel >> 1;
    const int selB = sel & 1;
    const int lrow = lane & 7;

    float acc[2][4][4];
#pragma unroll
    for (int t = 0; t < 2; t++)
#pragma unroll
        for (int j = 0; j < 4; j++)
#pragma unroll
            for (int e = 0; e < 4; e++) acc[t][j][e] = 0.f;

#pragma unroll
    for (int ks = 0; ks < 8; ks++) {
        unsigned ah[2][4], bh[4][2];
#pragma unroll
        for (int t = 0; t < 2; t++) {
            const int r = rA0 + t * 16;
            const unsigned off = (unsigned)(r * 256 + (((ks * 2 + khA) ^ (r & 7)) << 4));
            ldmx4(ah[t], sA0 + off);
        }
#pragma unroll
        for (int j = 0; j < 4; j++) {
            const int n = wn + j * 8 + lrow;
            const unsigned off = (unsigned)(n * 256 + (((ks * 2 + selB) ^ (n & 7)) << 4));
            ldmx2(bh[j], sB0 + off);
        }
#pragma unroll
        for (int t = 0; t < 2; t++)
#pragma unroll
            for (int j = 0; j < 4; j++)
                MMA16816(acc[t][j], ah[t], bh[j]);
    }

    const int g = lane >> 2, ct = lane & 3;
#pragma unroll
    for (int t = 0; t < 2; t++) {
        const int row = rowBase + wm + t * 16 + g;
#pragma unroll
        for (int j = 0; j < 4; j++) {
            const int cg = half * 1024 + nb * 64 + wn + j * 8 + ct * 2;
            __half* p = g_scoresh + (size_t)row * 2048 + cg;
            *(__half2*)p = __floats2half2_rn(acc[t][j][0], acc[t][j][1]);
            *(__half2*)(p + (size_t)8 * 2048) =
                __floats2half2_rn(acc[t][j][2], acc[t][j][3]);
        }
    }
}

// ---------------------------------------------------------------------------
// K4: selection — approx window -> segmented staged exact recompute ->
// bitonic exact order. Outputs bit-identical to the fp32 pipeline.
// ---------------------------------------------------------------------------
__device__ __forceinline__ void bitonic64(unsigned long long& a,
                                          unsigned long long& b, int lane)
{
#pragma unroll
    for (int k = 2; k <= 64; k <<= 1) {
#pragma unroll
        for (int j = 32; j >= 1; j >>= 1) {
            if (j >= k) continue;
            if (j == 32) {
                unsigned long long mx = a > b ? a : b;
                unsigned long long mn = a > b ? b : a;
                a = mx; b = mn;
            } else {
                const bool upa = ((lane & k) != 0);
                const bool upb = (((lane + 32) & k) != 0);
                const bool sel = ((lane & j) != 0);
                unsigned long long oa = __shfl_xor_sync(FULLMASK, a, j);
                unsigned long long ob = __shfl_xor_sync(FULLMASK, b, j);
                a = (sel == upa) ? (a > oa ? a : oa) : (a < oa ? a : oa);
                b = (sel == upb) ? (b > ob ? b : ob) : (b < ob ? b : ob);
            }
        }
    }
}

__device__ __forceinline__ void bitonic32(unsigned long long& a, int lane)
{
#pragma unroll
    for (int k = 2; k <= 32; k <<= 1) {
#pragma unroll
        for (int j = 16; j >= 1; j >>= 1) {
            if (j >= k) continue;
            const bool up = ((lane & k) != 0);   // k==32 -> false: descending
            const bool sel = ((lane & j) != 0);
            unsigned long long o = __shfl_xor_sync(FULLMASK, a, j);
            a = (sel == up) ? (a > o ? a : o) : (a < o ? a : o);
        }
    }
}

// staged exact dot for one segment of candidates smq[base..base+n).
// Returns exact key for lane < n, else 0. Warp-collective.
__device__ __forceinline__ unsigned long long seg_exact(
    float* __restrict__ wr, const float* __restrict__ kb,
    const unsigned long long* __restrict__ smq, int base, int n,
    int lane, const float* __restrict__ qn128)
{
    const int cl = (lane < n) ? lane : 0;
    float acc = 0.f;
#pragma unroll
    for (int ch = 0; ch < 2; ch++) {
        __syncwarp();
        for (int r = 0; r < n; r++) {
            const int idx = 1023 - (int)((unsigned)smq[base + r] & 0xFFFFu);
            const float* kr = kb + idx * 128 + ch * 64;
            wr[lane * NCP + r]        = kr[lane];
            wr[(lane + 32) * NCP + r] = kr[lane + 32];
        }
        __syncwarp();
        const float* qn = qn128 + ch * 64;
#pragma unroll
        for (int j = 0; j < 64; j += 4) {
            float4 qv = *(const float4*)(qn + j);
            acc = fmaf(qv.x, wr[(j + 0) * NCP + cl], acc);
            acc = fmaf(qv.y, wr[(j + 1) * NCP + cl], acc);
            acc = fmaf(qv.z, wr[(j + 2) * NCP + cl], acc);
            acc = fmaf(qv.w, wr[(j + 3) * NCP + cl], acc);
        }
    }
    return (lane < n)
        ? (((unsigned long long)fmono(acc) << 32)
           | ((unsigned long long)(unsigned)smq[base + lane] & 0xFFFFFFFFull))
        : 0ull;
}

// rare-path exact dot: per-lane LDG chain (k ascending)
__device__ __forceinline__ unsigned long long exact_key(
    unsigned long long key, bool act, const float* __restrict__ kb,
    const float* __restrict__ qs)
{
    unsigned long long r = 0ull;
    if (act) {
        const int idx = 1023 - (int)((unsigned)key & 0xFFFFu);
        const float4* kp = (const float4*)(kb + (size_t)idx * 128);
        float acc = 0.f;
#pragma unroll 4
        for (int j2 = 0; j2 < 32; j2++) {
            float4 bv = kp[j2];
            const float* qq = qs + j2 * 4;
            acc = fmaf(qq[0], bv.x, acc);
            acc = fmaf(qq[1], bv.y, acc);
            acc = fmaf(qq[2], bv.z, acc);
            acc = fmaf(qq[3], bv.w, acc);
        }
        r = ((unsigned long long)fmono(acc) << 32) | (key & 0xFFFFFFFFull);
    }
    return r;
}

__global__ __launch_bounds__(256)
void pkr_select(float* __restrict__ out, int Rtot,
                const float* __restrict__ ck, const float* __restrict__ cpk)
{
    extern __shared__ float smKr[];            // [8][64*NCP] dynamic (34816 B)
    __shared__ unsigned long long smQ[8][64];
    __shared__ unsigned long long smK[4][2][16];
    __shared__ float smQn[8][128];

    const int lane = threadIdx.x & 31;
    const int warp = threadIdx.x >> 5;
    const int r4   = warp >> 1;
    const int half = warp & 1;
    const int row  = blockIdx.x * 4 + r4;

    *(float4*)&smQn[warp][lane * 4] =
        *(const float4*)(g_qn + (size_t)row * 256 + half * 128 + lane * 4);
    __syncwarp();

    // load 1024 scaled fp16 approx scores -> float
    const uint2* bp = (const uint2*)(g_scoresh + (size_t)row * 2048 + half * 1024);
    float4 sv[8];
#pragma unroll
    for (int q2 = 0; q2 < 8; q2++) {
        uint2 u = bp[q2 * 32 + lane];
        float2 f0 = __half22float2(*(__half2*)&u.x);
        float2 f1 = __half22float2(*(__half2*)&u.y);
        sv[q2] = make_float4(f0.x, f0.y, f1.x, f1.y);
    }

    float vmax = -3.4e38f;
#pragma unroll
    for (int q2 = 0; q2 < 8; q2++)
        vmax = fmaxf(vmax, fmaxf(fmaxf(sv[q2].x, sv[q2].y), fmaxf(sv[q2].z, sv[q2].w)));
    float pmv = fmaxf(vmax, __shfl_xor_sync(FULLMASK, vmax, 1));
#pragma unroll
    for (int off = 2; off <= 16; off <<= 1)
        pmv = fminf(pmv, __shfl_xor_sync(FULLMASK, pmv, off));
    const float T0mE = pmv - EPS_SC;

    int cnt = 0;
#pragma unroll
    for (int q2 = 0; q2 < 8; q2++) {
        const float* vv = (const float*)&sv[q2];
#pragma unroll
        for (int t = 0; t < 4; t++) cnt += (vv[t] >= T0mE);
    }
    int inc = cnt;
#pragma unroll
    for (int off = 1; off <= 16; off <<= 1) {
        int n = __shfl_up_sync(FULLMASK, inc, off);
        if (lane >= off) inc += n;
    }
    const int total = __shfl_sync(FULLMASK, inc, 31);
    int myoff = inc - cnt;

    const int lbase = 1023 - lane * 4;
    unsigned long long a = 0ull, b = 0ull;
    bool done = false;
    const float* kb = half ? cpk : ck;

    if (total <= 64) {
        smQ[warp][lane] = 0ull;
        smQ[warp][lane + 32] = 0ull;
        __syncwarp();
#pragma unroll
        for (int q2 = 0; q2 < 8; q2++) {
            const float* vv = (const float*)&sv[q2];
#pragma unroll
            for (int t = 0; t < 4; t++) {
                const float v = vv[t];
                if (v >= T0mE) {
                    smQ[warp][myoff++] =
                        ((unsigned long long)fmono(v) << 32)
                        | (unsigned)(lbase - q2 * 128 - t);
                }
            }
        }
        __syncwarp();
        a = smQ[warp][lane];
        b = smQ[warp][lane + 32];
        bitonic64(a, b, lane);              // approx sorted desc

        // refined window below approx rank-16
        smQ[warp][lane] = a;                // sorted keys 0..31
        smQ[warp][lane + 32] = b;           // sorted keys 32..63
        __syncwarp();
        const unsigned long long a15 = __shfl_sync(FULLMASK, a, 15);
        const float thr = funmono((unsigned)(a15 >> 32)) - EPS_SC;
        const int nc =
            __popc(__ballot_sync(FULLMASK,
                (a != 0ull) && (funmono((unsigned)(a >> 32)) >= thr)))
          + __popc(__ballot_sync(FULLMASK,
                (b != 0ull) && (funmono((unsigned)(b >> 32)) >= thr)));

        if (nc <= 2 * NCP) {
            float* wr = smKr + warp * (64 * NCP);
            const int nc1 = (nc < NCP) ? nc : NCP;
            const int nc2 = nc - nc1;
            a = seg_exact(wr, kb, &smQ[warp][0], 0, nc1, lane, smQn[warp]);
            if (nc2 > 0) {
                b = seg_exact(wr, kb, &smQ[warp][0], nc1, nc2, lane, smQn[warp]);
                bitonic64(a, b, lane);      // exact order (score desc, idx asc)
            } else {
                bitonic32(a, lane);
            }
            done = true;
        }
    } else {
        // fallback: ballot-insert distributed approx top-32 (rare)
        unsigned long long rk = 0ull;
        float Tf = T0mE;
#pragma unroll
        for (int q2 = 0; q2 < 8; q2++) {
            const float* vv = (const float*)&sv[q2];
#pragma unroll
            for (int t = 0; t < 4; t++) {
                const float v = vv[t];
                const bool p = (v >= Tf);
                unsigned long long K = ((unsigned long long)fmono(v) << 32)
                                     | (unsigned)(lbase - q2 * 128 - t);
                unsigned bal = __ballot_sync(FULLMASK, p);
                while (bal) {
                    const int src = __ffs(bal) - 1;
                    bal &= bal - 1;
                    const unsigned long long Kc = __shfl_sync(FULLMASK, K, src);
                    const unsigned mg = __ballot_sync(FULLMASK, Kc > rk);
                    if (mg) {
                        const int pos = __ffs(mg) - 1;
                        const unsigned long long up = __shfl_up_sync(FULLMASK, rk, 1);
                        if (lane >= pos) rk = (lane == pos) ? Kc : up;
                    }
                    const unsigned long long T32 = __shfl_sync(FULLMASK, rk, 31);
                    Tf = fmaxf(T0mE, funmono((unsigned)(T32 >> 32)));
                }
            }
        }
        a = rk;
        b = 0ull;
    }

    if (!done) {
        // rare path: per-lane exact recompute of window candidates
        const unsigned long long a15 = __shfl_sync(FULLMASK, a, 15);
        const float thr = funmono((unsigned)(a15 >> 32)) - EPS_SC;
        const bool aa = (a != 0ull) && (funmono((unsigned)(a >> 32)) >= thr);
        const bool ab = (b != 0ull) && (funmono((unsigned)(b >> 32)) >= thr);
        a = exact_key(a, aa, kb, smQn[warp]);
        if (__ballot_sync(FULLMASK, ab)) b = exact_key(b, ab, kb, smQn[warp]);
        else b = 0ull;
        bitonic64(a, b, lane);
    }

    if (lane < 16) smK[r4][half][lane] = a;
    __syncthreads();

    // ---- joint stage: warps 0..3 each handle one row (exact scores) ----
    if (warp < 4) {
        const int jr = warp;
        const unsigned long long k1 = smK[jr][0][lane & 15];
        const unsigned long long k2 = smK[jr][1][lane & 15];
        const float s1c = funmono((unsigned)(k1 >> 32));
        const float s2c = funmono((unsigned)(k2 >> 32));
        const int e1v = 1023 - (int)((unsigned)k1 & 0xFFFFu);
        const int e2v = 1023 - (int)((unsigned)k2 & 0xFFFFu);
        const int jrow = blockIdx.x * 4 + jr;

        const int i0 = c_CI[lane], j0 = c_CJ[lane];
        const int cid1 = lane + 32;
        const bool v1 = (cid1 < 50);
        const int i1 = c_CI[v1 ? cid1 : 0], j1 = c_CJ[v1 ? cid1 : 0];

        const float a0 = __shfl_sync(FULLMASK, s1c, i0);
        const float b0 = __shfl_sync(FULLMASK, s2c, j0);
        const float a1 = __shfl_sync(FULLMASK, s1c, i1);
        const float b1 = __shfl_sync(FULLMASK, s2c, j1);

        unsigned long long K0 =
            ((unsigned long long)fmono(a0 + b0) << 32) | (unsigned)(4095 - (i0 * 64 + j0));
        unsigned long long K1 = v1
            ? (((unsigned long long)fmono(a1 + b1) << 32) | (unsigned)(4095 - (i1 * 64 + j1)))
            : 0ull;

        unsigned long long last = ~0ull;
        unsigned long long resKey = 0ull;
#pragma unroll
        for (int r = 0; r < 16; r++) {
            unsigned long long m = (K0 < last) ? K0 : 0ull;
            if (K1 < last && K1 > m) m = K1;
#pragma unroll
            for (int off = 16; off >= 1; off >>= 1) {
                const unsigned long long o = __shfl_xor_sync(FULLMASK, m, off);
                if (o > m) m = o;
            }
            last = m;
            if (lane == r) resKey = m;
        }

        const int flat = 4095 - (int)((unsigned)resKey & 0xFFFu);
        const int ri = (flat >> 6) & 31;
        const int rj = flat & 31;
        const int er = __shfl_sync(FULLMASK, e1v, ri);
        const int ec = __shfl_sync(FULLMASK, e2v, rj);

        if (lane < 16) {
            out[(size_t)jrow * 16 + lane] = (float)(er * 1024 + ec);
            out[(size_t)Rtot * 16 + (size_t)jrow * 16 + lane] =
                funmono((unsigned)(resKey >> 32));
        }
    }
}

// ---------------------------------------------------------------------------
extern "C" void kernel_launch(void* const* d_in, const int* in_sizes, int n_in,
                              void* d_out, int out_size)
{
    const float* q   = (const float*)d_in[0];
    const float* ck  = (const float*)d_in[1];
    const float* cpk = (const float*)d_in[2];
    const float* gm  = (const float*)d_in[3];
    const float* bt  = (const float*)d_in[4];

    const int R = in_sizes[0] / 256;  // 65536

    cudaFuncSetAttribute(pkr_mma, cudaFuncAttributeMaxDynamicSharedMemorySize, 49152);
    cudaFuncSetAttribute(pkr_select, cudaFuncAttributeMaxDynamicSharedMemorySize,
                         8 * 64 * NCP * 4);

    pkr_ln<<<R / 32, 256>>>(q, gm, bt);
    pkr_kprep<<<1024, 256>>>(ck, cpk);
    pkr_mma<<<dim3(32, R / 128), 256, 49152>>>();
    pkr_select<<<R / 4, 256, 8 * 64 * NCP * 4>>>((float*)d_out, R, ck, cpk);
}

// round 17
// speedup vs baseline: 1.2779x; 1.2779x over previous
#include <cuda_runtime.h>
#include <cuda_fp16.h>
#include <cstdint>

#define FULLMASK 0xffffffffu
#define R_TOT 65536

// approx scores are scaled by (2^4)*(2^8) = 4096
#define Q_SCALE  16.0f
#define K_SCALE  256.0f
#define EPS_SC   64.0f   // window (scaled): >= 2*(hh-only approx err + fp16 quant)
#define NCP      17      // staged-candidate cap; 45056B/CTA -> 5 CTA/SM

// ---------------- device scratch (no allocs allowed) ----------------
__device__ __align__(16) __half g_scoresh[(size_t)R_TOT * 2048];   // 256MB approx
__device__ __align__(16) float g_qn[(size_t)R_TOT * 256];          // exact q_norm
__device__ __align__(16) __half g_qh[(size_t)2 * R_TOT * 128];
__device__ __align__(16) __half g_kh[2 * 1024 * 128];

// Joint candidates: (i+1)*(j+1) <= 16 -> 50 cells
__constant__ unsigned char c_CI[50] = {
    0,0,0,0,0,0,0,0,0,0,0,0,0,0,0,0, 1,1,1,1,1,1,1,1, 2,2,2,2,2,
    3,3,3,3, 4,4,4, 5,5, 6,6, 7,7, 8,9,10,11,12,13,14,15
};
__constant__ unsigned char c_CJ[50] = {
    0,1,2,3,4,5,6,7,8,9,10,11,12,13,14,15, 0,1,2,3,4,5,6,7, 0,1,2,3,4,
    0,1,2,3, 0,1,2, 0,1, 0,1, 0,1, 0,0,0,0,0,0,0,0
};

__device__ __forceinline__ unsigned fmono(float f) {
    unsigned u = __float_as_uint(f);
    return u ^ (unsigned)(((int)u >> 31) | (int)0x80000000);
}
__device__ __forceinline__ float funmono(unsigned m) {
    return __uint_as_float((m & 0x80000000u) ? (m ^ 0x80000000u) : ~m);
}

// ---------------------------------------------------------------------------
// K1: LayerNorm — BIT-EXACT R1/R5 numerics. Writes exact fp32 q_norm and
// scaled fp16 (hi term only) for the HMMA oracle.
// ---------------------------------------------------------------------------
__global__ __launch_bounds__(256)
void pkr_ln(const float* __restrict__ query,
            const float* __restrict__ gma,
            const float* __restrict__ bta)
{
    const int tid = threadIdx.x;
    const int r = tid >> 3, g = tid & 7;
    const int row = blockIdx.x * 32 + r;

    const float4* qp = (const float4*)(query + (size_t)row * 256);
    float4 v[8];
    float s = 0.f;
#pragma unroll
    for (int j = 0; j < 8; j++) {
        v[j] = qp[j * 8 + g];
        s += (v[j].x + v[j].y) + (v[j].z + v[j].w);
    }
#pragma unroll
    for (int off = 4; off >= 1; off >>= 1)
        s += __shfl_xor_sync(FULLMASK, s, off, 8);
    const float mu = s * (1.f / 256.f);

    float s2 = 0.f;
#pragma unroll
    for (int j = 0; j < 8; j++) {
        float dx = v[j].x - mu, dy = v[j].y - mu;
        float dz = v[j].z - mu, dw = v[j].w - mu;
        s2 += (dx * dx + dy * dy) + (dz * dz + dw * dw);
    }
#pragma unroll
    for (int off = 4; off >= 1; off >>= 1)
        s2 += __shfl_xor_sync(FULLMASK, s2, off, 8);

    const float varp = s2 * (1.f / 256.f) + 1e-5f;
    float rs = rsqrtf(varp);
    rs = rs * (1.5f - 0.5f * varp * rs * rs);

#pragma unroll
    for (int j = 0; j < 8; j++) {
        const int c = j * 32 + g * 4;
        float d0 = (v[j].x - mu) * rs * gma[c + 0] + bta[c + 0];
        float d1 = (v[j].y - mu) * rs * gma[c + 1] + bta[c + 1];
        float d2 = (v[j].z - mu) * rs * gma[c + 2] + bta[c + 2];
        float d3 = (v[j].w - mu) * rs * gma[c + 3] + bta[c + 3];

        *(float4*)(g_qn + (size_t)row * 256 + c) = make_float4(d0, d1, d2, d3);

        union { __half b[4]; uint2 u; } ph;
        ph.b[0] = __float2half_rn(d0 * Q_SCALE);
        ph.b[1] = __float2half_rn(d1 * Q_SCALE);
        ph.b[2] = __float2half_rn(d2 * Q_SCALE);
        ph.b[3] = __float2half_rn(d3 * Q_SCALE);
        const int half = c >> 7, kl = c & 127;
        *(uint2*)(g_qh + (size_t)half * R_TOT * 128 + (size_t)row * 128 + kl) = ph.u;
    }
}

// ---------------------------------------------------------------------------
// K2: scaled fp16 (hi only) of both key matrices.
// ---------------------------------------------------------------------------
__global__ void pkr_kprep(const float* __restrict__ ck, const float* __restrict__ cp)
{
    const int idx = blockIdx.x * 256 + threadIdx.x;      // 0..262143
    float vv = ((idx < 131072) ? ck[idx] : cp[idx - 131072]) * K_SCALE;
    g_kh[idx] = __float2half_rn(vv);
}

// ---------------------------------------------------------------------------
// K3: 1-product fp16 HMMA GEMM (approx oracle). BM=128, BN=64, 8 warps.
// ---------------------------------------------------------------------------
#define MMA16816(d, a, b)                                                       \
    asm volatile("mma.sync.aligned.m16n8k16.row.col.f32.f16.f16.f32 "           \
                 "{%0,%1,%2,%3}, {%4,%5,%6,%7}, {%8,%9}, {%0,%1,%2,%3};"        \
                 : "+f"(d[0]), "+f"(d[1]), "+f"(d[2]), "+f"(d[3])               \
                 : "r"(a[0]), "r"(a[1]), "r"(a[2]), "r"(a[3]),                  \
                   "r"(b[0]), "r"(b[1]))

__device__ __forceinline__ void ldmx4(unsigned* r, unsigned addr) {
    asm volatile("ldmatrix.sync.aligned.m8n8.x4.shared.b16 {%0,%1,%2,%3}, [%4];"
                 : "=r"(r[0]), "=r"(r[1]), "=r"(r[2]), "=r"(r[3]) : "r"(addr));
}
__device__ __forceinline__ void ldmx2(unsigned* r, unsigned addr) {
    asm volatile("ldmatrix.sync.aligned.m8n8.x2.shared.b16 {%0,%1}, [%2];"
                 : "=r"(r[0]), "=r"(r[1]) : "r"(addr));
}

__global__ __launch_bounds__(256, 4)
void pkr_mma(void)
{
    extern __shared__ char sm[];
    // Ah 0..32K, Bh 32K..48K
    const unsigned sA0 = (unsigned)__cvta_generic_to_shared(sm);
    const unsigned sB0 = sA0 + 32768;

    const int tid  = threadIdx.x;
    const int half = blockIdx.x >> 4;
    const int nb   = blockIdx.x & 15;
    const int rowBase = blockIdx.y * 128;

    {
        const int r = tid >> 1, c0 = (tid & 1) * 8;
        const uint4* glh = (const uint4*)(g_qh + (size_t)half * R_TOT * 128
                                          + (size_t)(rowBase + r) * 128);
        char* base = sm + r * 256;
#pragma unroll
        for (int i = 0; i < 8; i++) {
            const int c = c0 + i, cp = c ^ (r & 7);
            *(uint4*)(base + cp * 16) = glh[c];
        }
    }
    {
        const int r = tid >> 2, c0 = (tid & 3) * 4;
        const uint4* glh = (const uint4*)(g_kh + (size_t)half * 1024 * 128
                                          + (size_t)(nb * 64 + r) * 128);
        char* base = sm + 32768 + r * 256;
#pragma unroll
        for (int i = 0; i < 4; i++) {
            const int c = c0 + i, cp = c ^ (r & 7);
            *(uint4*)(base + cp * 16) = glh[c];
        }
    }
    __syncthreads();

    const int warp = tid >> 5, lane = tid & 31;
    const int wm = (warp >> 1) * 32;
    const int wn = (warp & 1) * 32;
    const int sel = lane >> 3;

    const int rA0 = wm + (lane & 7) + ((sel & 1) << 3);
    const int khA = sel >> 1;
    const int selB = sel & 1;
    const int lrow = lane & 7;

    float acc[2][4][4];
#pragma unroll
    for (int t = 0; t < 2; t++)
#pragma unroll
        for (int j = 0; j < 4; j++)
#pragma unroll
            for (int e = 0; e < 4; e++) acc[t][j][e] = 0.f;

#pragma unroll
    for (int ks = 0; ks < 8; ks++) {
        unsigned ah[2][4], bh[4][2];
#pragma unroll
        for (int t = 0; t < 2; t++) {
            const int r = rA0 + t * 16;
            const unsigned off = (unsigned)(r * 256 + (((ks * 2 + khA) ^ (r & 7)) << 4));
            ldmx4(ah[t], sA0 + off);
        }
#pragma unroll
        for (int j = 0; j < 4; j++) {
            const int n = wn + j * 8 + lrow;
            const unsigned off = (unsigned)(n * 256 + (((ks * 2 + selB) ^ (n & 7)) << 4));
            ldmx2(bh[j], sB0 + off);
        }
#pragma unroll
        for (int t = 0; t < 2; t++)
#pragma unroll
            for (int j = 0; j < 4; j++)
                MMA16816(acc[t][j], ah[t], bh[j]);
    }

    const int g = lane >> 2, ct = lane & 3;
#pragma unroll
    for (int t = 0; t < 2; t++) {
        const int row = rowBase + wm + t * 16 + g;
#pragma unroll
        for (int j = 0; j < 4; j++) {
            const int cg = half * 1024 + nb * 64 + wn + j * 8 + ct * 2;
            __half* p = g_scoresh + (size_t)row * 2048 + cg;
            *(__half2*)p = __floats2half2_rn(acc[t][j][0], acc[t][j][1]);
            *(__half2*)(p + (size_t)8 * 2048) =
                __floats2half2_rn(acc[t][j][2], acc[t][j][3]);
        }
    }
}

// ---------------------------------------------------------------------------
// K4: selection — approx window -> conflict-free staged exact recompute ->
// bitonic32 exact order. Outputs bit-identical to the fp32 pipeline.
// (R13/R15-proven structure: regs 48, single-segment fast path.)
// ---------------------------------------------------------------------------
__device__ __forceinline__ void bitonic64(unsigned long long& a,
                                          unsigned long long& b, int lane)
{
#pragma unroll
    for (int k = 2; k <= 64; k <<= 1) {
#pragma unroll
        for (int j = 32; j >= 1; j >>= 1) {
            if (j >= k) continue;
            if (j == 32) {
                unsigned long long mx = a > b ? a : b;
                unsigned long long mn = a > b ? b : a;
                a = mx; b = mn;
            } else {
                const bool upa = ((lane & k) != 0);
                const bool upb = (((lane + 32) & k) != 0);
                const bool sel = ((lane & j) != 0);
                unsigned long long oa = __shfl_xor_sync(FULLMASK, a, j);
                unsigned long long ob = __shfl_xor_sync(FULLMASK, b, j);
                a = (sel == upa) ? (a > oa ? a : oa) : (a < oa ? a : oa);
                b = (sel == upb) ? (b > ob ? b : ob) : (b < ob ? b : ob);
            }
        }
    }
}

__device__ __forceinline__ void bitonic32(unsigned long long& a, int lane)
{
#pragma unroll
    for (int k = 2; k <= 32; k <<= 1) {
#pragma unroll
        for (int j = 16; j >= 1; j >>= 1) {
            if (j >= k) continue;
            const bool up = ((lane & k) != 0);   // k==32 -> false: descending
            const bool sel = ((lane & j) != 0);
            unsigned long long o = __shfl_xor_sync(FULLMASK, a, j);
            a = (sel == up) ? (a > o ? a : o) : (a < o ? a : o);
        }
    }
}

// rare-path exact dot: per-lane sequential LDG chain (k ascending)
__device__ __forceinline__ unsigned long long exact_key(
    unsigned long long key, bool act, const float* __restrict__ kb,
    const float* __restrict__ qs)
{
    unsigned long long r = 0ull;
    if (act) {
        const int idx = 1023 - (int)((unsigned)key & 0xFFFFu);
        const float4* kp = (const float4*)(kb + (size_t)idx * 128);
        float acc = 0.f;
#pragma unroll 4
        for (int j2 = 0; j2 < 32; j2++) {
            float4 bv = kp[j2];
            const float* qq = qs + j2 * 4;
            acc = fmaf(qq[0], bv.x, acc);
            acc = fmaf(qq[1], bv.y, acc);
            acc = fmaf(qq[2], bv.z, acc);
            acc = fmaf(qq[3], bv.w, acc);
        }
        r = ((unsigned long long)fmono(acc) << 32) | (key & 0xFFFFFFFFull);
    }
    return r;
}

__global__ __launch_bounds__(256)
void pkr_select(float* __restrict__ out, int Rtot,
                const float* __restrict__ ck, const float* __restrict__ cpk)
{
    extern __shared__ float smKr[];            // [8][64*NCP] dynamic (34816 B)
    __shared__ unsigned long long smQ[8][64];
    __shared__ unsigned long long smK[4][2][16];
    __shared__ float smQn[8][128];

    const int lane = threadIdx.x & 31;
    const int warp = threadIdx.x >> 5;
    const int r4   = warp >> 1;
    const int half = warp & 1;
    const int row  = blockIdx.x * 4 + r4;

    *(float4*)&smQn[warp][lane * 4] =
        *(const float4*)(g_qn + (size_t)row * 256 + half * 128 + lane * 4);
    __syncwarp();

    // load 1024 scaled fp16 approx scores -> float
    const uint2* bp = (const uint2*)(g_scoresh + (size_t)row * 2048 + half * 1024);
    float4 sv[8];
#pragma unroll
    for (int q2 = 0; q2 < 8; q2++) {
        uint2 u = bp[q2 * 32 + lane];
        float2 f0 = __half22float2(*(__half2*)&u.x);
        float2 f1 = __half22float2(*(__half2*)&u.y);
        sv[q2] = make_float4(f0.x, f0.y, f1.x, f1.y);
    }

    float vmax = -3.4e38f;
#pragma unroll
    for (int q2 = 0; q2 < 8; q2++)
        vmax = fmaxf(vmax, fmaxf(fmaxf(sv[q2].x, sv[q2].y), fmaxf(sv[q2].z, sv[q2].w)));
    float pmv = fmaxf(vmax, __shfl_xor_sync(FULLMASK, vmax, 1));
#pragma unroll
    for (int off = 2; off <= 16; off <<= 1)
        pmv = fminf(pmv, __shfl_xor_sync(FULLMASK, pmv, off));
    const float T0mE = pmv - EPS_SC;

    int cnt = 0;
#pragma unroll
    for (int q2 = 0; q2 < 8; q2++) {
        const float* vv = (const float*)&sv[q2];
#pragma unroll
        for (int t = 0; t < 4; t++) cnt += (vv[t] >= T0mE);
    }
    int inc = cnt;
#pragma unroll
    for (int off = 1; off <= 16; off <<= 1) {
        int n = __shfl_up_sync(FULLMASK, inc, off);
        if (lane >= off) inc += n;
    }
    const int total = __shfl_sync(FULLMASK, inc, 31);
    int myoff = inc - cnt;

    const int lbase = 1023 - lane * 4;
    unsigned long long a = 0ull, b = 0ull;
    bool done = false;
    const float* kb = half ? cpk : ck;

    if (total <= 64) {
        smQ[warp][lane] = 0ull;
        smQ[warp][lane + 32] = 0ull;
        __syncwarp();
#pragma unroll
        for (int q2 = 0; q2 < 8; q2++) {
            const float* vv = (const float*)&sv[q2];
#pragma unroll
            for (int t = 0; t < 4; t++) {
                const float v = vv[t];
                if (v >= T0mE) {
                    smQ[warp][myoff++] =
                        ((unsigned long long)fmono(v) << 32)
                        | (unsigned)(lbase - q2 * 128 - t);
                }
            }
        }
        __syncwarp();
        a = smQ[warp][lane];
        b = smQ[warp][lane + 32];
        bitonic64(a, b, lane);              // approx sorted desc

        const unsigned long long a15 = __shfl_sync(FULLMASK, a, 15);
        const float thr = funmono((unsigned)(a15 >> 32)) - EPS_SC;
        const bool aok = (a != 0ull) && (funmono((unsigned)(a >> 32)) >= thr);
        const int nc = __popc(__ballot_sync(FULLMASK, aok));
        const bool bany = __ballot_sync(FULLMASK,
            (b != 0ull) && (funmono((unsigned)(b >> 32)) >= thr)) != 0u;

        if (!bany && nc <= NCP) {
            // ---- fast path: staged exact recompute ----
            smQ[warp][lane] = a;            // sorted approx keys
            __syncwarp();
            float* wr = smKr + warp * (64 * NCP);
            const int cl = (lane < NCP) ? lane : 0;
            float acc = 0.f;
#pragma unroll
            for (int ch = 0; ch < 2; ch++) {
                __syncwarp();
                for (int r = 0; r < nc; r++) {
                    const int idx = 1023 - (int)((unsigned)smQ[warp][r] & 0xFFFFu);
                    const float* kr = kb + idx * 128 + ch * 64;
                    wr[lane * NCP + r]        = kr[lane];
                    wr[(lane + 32) * NCP + r] = kr[lane + 32];
                }
                __syncwarp();
                const float* qn = &smQn[warp][ch * 64];
#pragma unroll
                for (int j = 0; j < 64; j += 4) {
                    float4 qv = *(const float4*)(qn + j);
                    acc = fmaf(qv.x, wr[(j + 0) * NCP + cl], acc);
                    acc = fmaf(qv.y, wr[(j + 1) * NCP + cl], acc);
                    acc = fmaf(qv.z, wr[(j + 2) * NCP + cl], acc);
                    acc = fmaf(qv.w, wr[(j + 3) * NCP + cl], acc);
                }
            }
            a = (lane < nc)
                ? (((unsigned long long)fmono(acc) << 32)
                   | ((unsigned long long)(unsigned)smQ[warp][lane] & 0xFFFFFFFFull))
                : 0ull;
            bitonic32(a, lane);             // exact order (score desc, idx asc)
            done = true;
        }
    } else {
        // fallback: ballot-insert distributed approx top-32 (rare)
        unsigned long long rk = 0ull;
        float Tf = T0mE;
#pragma unroll
        for (int q2 = 0; q2 < 8; q2++) {
            const float* vv = (const float*)&sv[q2];
#pragma unroll
            for (int t = 0; t < 4; t++) {
                const float v = vv[t];
                const bool p = (v >= Tf);
                unsigned long long K = ((unsigned long long)fmono(v) << 32)
                                     | (unsigned)(lbase - q2 * 128 - t);
                unsigned bal = __ballot_sync(FULLMASK, p);
                while (bal) {
                    const int src = __ffs(bal) - 1;
                    bal &= bal - 1;
                    const unsigned long long Kc = __shfl_sync(FULLMASK, K, src);
                    const unsigned mg = __ballot_sync(FULLMASK, Kc > rk);
                    if (mg) {
                        const int pos = __ffs(mg) - 1;
                        const unsigned long long up = __shfl_up_sync(FULLMASK, rk, 1);
                        if (lane >= pos) rk = (lane == pos) ? Kc : up;
                    }
                    const unsigned long long T32 = __shfl_sync(FULLMASK, rk, 31);
                    Tf = fmaxf(T0mE, funmono((unsigned)(T32 >> 32)));
                }
            }
        }
        a = rk;
        b = 0ull;
    }

    if (!done) {
        // rare path: per-lane exact recompute of window candidates
        const unsigned long long a15 = __shfl_sync(FULLMASK, a, 15);
        const float thr = funmono((unsigned)(a15 >> 32)) - EPS_SC;
        const bool aa = (a != 0ull) && (funmono((unsigned)(a >> 32)) >= thr);
        const bool ab = (b != 0ull) && (funmono((unsigned)(b >> 32)) >= thr);
        a = exact_key(a, aa, kb, smQn[warp]);
        if (__ballot_sync(FULLMASK, ab)) b = exact_key(b, ab, kb, smQn[warp]);
        else b = 0ull;
        bitonic64(a, b, lane);
    }

    if (lane < 16) smK[r4][half][lane] = a;
    __syncthreads();

    // ---- joint stage: warps 0..3 each handle one row (exact scores) ----
    if (warp < 4) {
        const int jr = warp;
        const unsigned long long k1 = smK[jr][0][lane & 15];
        const unsigned long long k2 = smK[jr][1][lane & 15];
        const float s1c = funmono((unsigned)(k1 >> 32));
        const float s2c = funmono((unsigned)(k2 >> 32));
        const int e1v = 1023 - (int)((unsigned)k1 & 0xFFFFu);
        const int e2v = 1023 - (int)((unsigned)k2 & 0xFFFFu);
        const int jrow = blockIdx.x * 4 + jr;

        const int i0 = c_CI[lane], j0 = c_CJ[lane];
        const int cid1 = lane + 32;
        const bool v1 = (cid1 < 50);
        const int i1 = c_CI[v1 ? cid1 : 0], j1 = c_CJ[v1 ? cid1 : 0];

        const float a0 = __shfl_sync(FULLMASK, s1c, i0);
        const float b0 = __shfl_sync(FULLMASK, s2c, j0);
        const float a1 = __shfl_sync(FULLMASK, s1c, i1);
        const float b1 = __shfl_sync(FULLMASK, s2c, j1);

        unsigned long long K0 =
            ((unsigned long long)fmono(a0 + b0) << 32) | (unsigned)(4095 - (i0 * 64 + j0));
        unsigned long long K1 = v1
            ? (((unsigned long long)fmono(a1 + b1) << 32) | (unsigned)(4095 - (i1 * 64 + j1)))
            : 0ull;

        unsigned long long last = ~0ull;
        unsigned long long resKey = 0ull;
#pragma unroll
        for (int r = 0; r < 16; r++) {
            unsigned long long m = (K0 < last) ? K0 : 0ull;
            if (K1 < last && K1 > m) m = K1;
#pragma unroll
            for (int off = 16; off >= 1; off >>= 1) {
                const unsigned long long o = __shfl_xor_sync(FULLMASK, m, off);
                if (o > m) m = o;
            }
            last = m;
            if (lane == r) resKey = m;
        }

        const int flat = 4095 - (int)((unsigned)resKey & 0xFFFu);
        const int ri = (flat >> 6) & 31;
        const int rj = flat & 31;
        const int er = __shfl_sync(FULLMASK, e1v, ri);
        const int ec = __shfl_sync(FULLMASK, e2v, rj);

        if (lane < 16) {
            out[(size_t)jrow * 16 + lane] = (float)(er * 1024 + ec);
            out[(size_t)Rtot * 16 + (size_t)jrow * 16 + lane] =
                funmono((unsigned)(resKey >> 32));
        }
    }
}

// ---------------------------------------------------------------------------
extern "C" void kernel_launch(void* const* d_in, const int* in_sizes, int n_in,
                              void* d_out, int out_size)
{
    const float* q   = (const float*)d_in[0];
    const float* ck  = (const float*)d_in[1];
    const float* cpk = (const float*)d_in[2];
    const float* gm  = (const float*)d_in[3];
    const float* bt  = (const float*)d_in[4];

    const int R = in_sizes[0] / 256;  // 65536

    cudaFuncSetAttribute(pkr_mma, cudaFuncAttributeMaxDynamicSharedMemorySize, 49152);
    cudaFuncSetAttribute(pkr_select, cudaFuncAttributeMaxDynamicSharedMemorySize,
                         8 * 64 * NCP * 4);

    pkr_ln<<<R / 32, 256>>>(q, gm, bt);
    pkr_kprep<<<1024, 256>>>(ck, cpk);
    pkr_mma<<<dim3(32, R / 128), 256, 49152>>>();
    pkr_select<<<R / 4, 256, 8 * 64 * NCP * 4>>>((float*)d_out, R, ck, cpk);
}